// round 9
// baseline (speedup 1.0000x reference)
#include <cuda_runtime.h>
#include <cuda_bf16.h>
#include <math.h>

// Problem constants (fixed by the dataset)
#define MAXN 50000
#define MAXE 800000
#define F_DIM 128
#define H_DIM 256
#define L_DIM 64
#define V_DIM 128
#define SCAN_B 64   // max scan blocks (ceil(50000/1024)=49)

// ---------------- scratch (allocation-free: __device__ globals) ----------------
__device__ int    g_cnt[MAXN + 1];
__device__ int    g_rowptr[MAXN + 1];
__device__ float  g_dinv[MAXN];
__device__ int    g_bsum[SCAN_B];
__device__ int    g_boff[SCAN_B];
__device__ float2 g_e1[MAXE];   // (x[src] as float-bits, dinv[src])  — layer-1 edges
__device__ float2 g_e2[MAXE];   // (src as float-bits,   dinv[src])  — layer-2 edges
__device__ float  g_ew1[V_DIM * H_DIM];           // emb @ W1  [128,256]
__device__ float  g_wmulv[H_DIM * (2 * L_DIM)];   // [Wmu | Wlv]  [256,128]
__device__ float  g_bmulv[2 * L_DIM];
__device__ float  g_bufA[(size_t)MAXN * H_DIM];   // XW2 / ZR
__device__ float  g_bufB[(size_t)MAXN * H_DIM];   // h1 / h2
__device__ float  g_z[(size_t)MAXN * L_DIM];

// ---------------- f32x2 packed-FMA helpers (Blackwell double-rate fp32) ----------------
#define FFMA2(acc, a, b) \
    asm("fma.rn.f32x2 %0, %1, %2, %0;" : "+l"(acc) : "l"(a), "l"(b))

__device__ __forceinline__ unsigned long long splat_f32x2(float v) {
    unsigned long long r;
    unsigned int u = __float_as_uint(v);
    asm("mov.b64 %0, {%1, %2};" : "=l"(r) : "r"(u), "r"(u));
    return r;
}

// ---------------- graph build ----------------
__global__ void k_zero_cnt(int n) {
    int i = blockIdx.x * blockDim.x + threadIdx.x;
    if (i <= n) g_cnt[i] = 0;
}

__global__ void k_count(const int* __restrict__ ei, int E) {
    int e = blockIdx.x * blockDim.x + threadIdx.x;
    if (e < E) atomicAdd(&g_cnt[ei[E + e]], 1);  // dst row
}

__global__ void k_dinv(int n) {
    int i = blockIdx.x * blockDim.x + threadIdx.x;
    if (i < n) g_dinv[i] = rsqrtf((float)(g_cnt[i] + 1));  // +1 self-loop
}

// pass 1: per-block exclusive scan of g_cnt -> g_rowptr (block-local), block sums -> g_bsum.
// also zeroes g_cnt (reused as fill cursor).
__global__ void k_scan1(int n) {
    __shared__ int sh[1024];
    int t = threadIdx.x;
    int i = blockIdx.x * 1024 + t;
    int v = (i < n) ? g_cnt[i] : 0;
    sh[t] = v;
    __syncthreads();
    for (int off = 1; off < 1024; off <<= 1) {
        int add = (t >= off) ? sh[t - off] : 0;
        __syncthreads();
        sh[t] += add;
        __syncthreads();
    }
    if (i < n) { g_rowptr[i] = sh[t] - v; g_cnt[i] = 0; }
    if (t == 1023) g_bsum[blockIdx.x] = sh[1023];
}

// pass 2: scan the (<=64) block sums, write rowptr[n]
__global__ void k_scan2(int n, int nb) {
    __shared__ int sh[SCAN_B];
    int t = threadIdx.x;  // 64 threads
    int v = (t < nb) ? g_bsum[t] : 0;
    sh[t] = v;
    __syncthreads();
    for (int off = 1; off < SCAN_B; off <<= 1) {
        int add = (t >= off) ? sh[t - off] : 0;
        __syncthreads();
        sh[t] += add;
        __syncthreads();
    }
    if (t < nb) g_boff[t] = sh[t] - v;        // exclusive (race-free)
    if (t == SCAN_B - 1) g_rowptr[n] = sh[SCAN_B - 1];
}

// pass 3: add block offsets
__global__ void k_scan3(int n) {
    int i = blockIdx.x * 1024 + threadIdx.x;
    if (i < n) g_rowptr[i] += g_boff[blockIdx.x];
}

__global__ void k_fill(const int* __restrict__ ei, const int* __restrict__ x, int E) {
    int e = blockIdx.x * blockDim.x + threadIdx.x;
    if (e < E) {
        int s = ei[e];
        int d = ei[E + e];
        int pos = g_rowptr[d] + atomicAdd(&g_cnt[d], 1);
        float w = g_dinv[s];
        g_e2[pos] = make_float2(__int_as_float(s), w);
        g_e1[pos] = make_float2(__int_as_float(x[s]), w);
    }
}

// ---------------- layer 1 ----------------
// EW1[v,h] = sum_k emb[v,k] * W1[k,h]   (128x128 @ 128x256)
__global__ void k_ew1(const float* __restrict__ emb, const float* __restrict__ W1) {
    int v = blockIdx.x;     // 128
    int h = threadIdx.x;    // 256
    float acc = 0.f;
#pragma unroll 8
    for (int k = 0; k < F_DIM; k++) acc += emb[v * F_DIM + k] * W1[k * H_DIM + h];
    g_ew1[v * H_DIM + h] = acc;
}

// ---------------- vectorized aggregation: 4 nodes/block, 64 threads/node, float4 ----------------
// MODE 0: layer 1 — rows come from the L1-resident EW1 table, edge payload = (x[src], dinv[src])
// MODE 1: layer 2 — rows come from `in` (L2-resident), edge payload = (src, dinv[src])
template <int MODE>
__global__ void __launch_bounds__(256)
k_aggv(const int* __restrict__ x, const float* __restrict__ in,
       const float* __restrict__ bias, float* __restrict__ out, int n) {
    int node = blockIdx.x * 4 + (threadIdx.x >> 6);
    int f4 = threadIdx.x & 63;   // float4 lane: covers 256 floats
    if (node >= n) return;
    float di = g_dinv[node];
    const float4* tab = (MODE == 0) ? (const float4*)g_ew1 : (const float4*)in;

    int self = (MODE == 0) ? x[node] : node;
    float4 a = tab[(size_t)self * 64 + f4];
    float4 acc;
    acc.x = a.x * di; acc.y = a.y * di; acc.z = a.z * di; acc.w = a.w * di;

    int beg = g_rowptr[node], end = g_rowptr[node + 1];
    const float2* el = (MODE == 0) ? g_e1 : g_e2;
    for (int e = beg; e < end; e++) {
        float2 p = el[e];
        int s = __float_as_int(p.x);
        float w = p.y;
        float4 r = tab[(size_t)s * 64 + f4];
        acc.x = fmaf(r.x, w, acc.x);
        acc.y = fmaf(r.y, w, acc.y);
        acc.z = fmaf(r.z, w, acc.z);
        acc.w = fmaf(r.w, w, acc.w);
    }
    float4 b4 = ((const float4*)bias)[f4];
    float4 o;
    o.x = fmaxf(fmaf(di, acc.x, b4.x), 0.f);
    o.y = fmaxf(fmaf(di, acc.y, b4.y), 0.f);
    o.z = fmaxf(fmaf(di, acc.z, b4.z), 0.f);
    o.w = fmaxf(fmaf(di, acc.w, b4.w), 0.f);
    ((float4*)out)[(size_t)node * 64 + f4] = o;
}

// ---------------- packed-f32x2 SGEMM ----------------
// C[M,Nc] = A[M,K] @ B[K,Nc] (+bias)(+relu). BM=128 BN=64 BK=16, 256 thr,
// per-thread 8 rows x 4 cols as 4 row-pairs x 4 cols of f32x2 accumulators.
// Each FFMA2 lane is an exact IEEE fp32 FMA (.rn) — bit-identical to scalar chain.
// K%16==0, Nc%64==0. SPLIT: cols [0,64)->C, [64,128)->C2 (each row-stride 64).
template <int ACT, int SPLIT>
__global__ void __launch_bounds__(256)
k_gemm(const float* __restrict__ A, const float* __restrict__ B,
       const float* __restrict__ bias, float* __restrict__ C, float* __restrict__ C2,
       int M, int K, int Nc) {
    constexpr int BM = 128, BN = 64, BK = 16;
    __shared__ __align__(16) float As[BK][BM];      // transposed: As[k][m]
    __shared__ __align__(16) float Bs[BK][BN + 4];  // row stride 68 floats (272B, 16B-aligned)
    int t = threadIdx.x;
    int rb = blockIdx.x * BM;
    int cb = blockIdx.y * BN;

    unsigned long long acc[4][4];
#pragma unroll
    for (int p = 0; p < 4; p++)
#pragma unroll
        for (int j = 0; j < 4; j++) acc[p][j] = 0ULL;

    int arow = t >> 2;          // 0..63
    int acol = (t & 3) * 4;     // 0,4,8,12
    int brow = t >> 4;          // 0..15
    int bcol = (t & 15) * 4;    // 0..60
    int tm = t >> 4;            // 0..15 (row group of 8)
    int tn = t & 15;            // 0..15 (col group of 4)

    for (int kb = 0; kb < K; kb += BK) {
#pragma unroll
        for (int rr = 0; rr < 2; rr++) {
            int r = arow + rr * 64;
            int gr = rb + r;
            float4 v = make_float4(0.f, 0.f, 0.f, 0.f);
            if (gr < M) v = *(const float4*)&A[(size_t)gr * K + kb + acol];
            As[acol + 0][r] = v.x;
            As[acol + 1][r] = v.y;
            As[acol + 2][r] = v.z;
            As[acol + 3][r] = v.w;
        }
        *(float4*)&Bs[brow][bcol] = *(const float4*)&B[(size_t)(kb + brow) * Nc + cb + bcol];
        __syncthreads();

#pragma unroll
        for (int k = 0; k < BK; k++) {
            ulonglong2 a01 = *(const ulonglong2*)&As[k][tm * 8];      // row pairs (0,1),(2,3)
            ulonglong2 a23 = *(const ulonglong2*)&As[k][tm * 8 + 4];  // row pairs (4,5),(6,7)
            float4 bv = *(const float4*)&Bs[k][tn * 4];
            unsigned long long bp0 = splat_f32x2(bv.x);
            unsigned long long bp1 = splat_f32x2(bv.y);
            unsigned long long bp2 = splat_f32x2(bv.z);
            unsigned long long bp3 = splat_f32x2(bv.w);
            FFMA2(acc[0][0], a01.x, bp0); FFMA2(acc[0][1], a01.x, bp1);
            FFMA2(acc[0][2], a01.x, bp2); FFMA2(acc[0][3], a01.x, bp3);
            FFMA2(acc[1][0], a01.y, bp0); FFMA2(acc[1][1], a01.y, bp1);
            FFMA2(acc[1][2], a01.y, bp2); FFMA2(acc[1][3], a01.y, bp3);
            FFMA2(acc[2][0], a23.x, bp0); FFMA2(acc[2][1], a23.x, bp1);
            FFMA2(acc[2][2], a23.x, bp2); FFMA2(acc[2][3], a23.x, bp3);
            FFMA2(acc[3][0], a23.y, bp0); FFMA2(acc[3][1], a23.y, bp1);
            FFMA2(acc[3][2], a23.y, bp2); FFMA2(acc[3][3], a23.y, bp3);
        }
        __syncthreads();
    }

#pragma unroll
    for (int p = 0; p < 4; p++) {
#pragma unroll
        for (int h = 0; h < 2; h++) {
            int gr = rb + tm * 8 + 2 * p + h;
            if (gr >= M) continue;
#pragma unroll
            for (int j = 0; j < 4; j++) {
                unsigned int bits = (h == 0) ? (unsigned int)(acc[p][j] & 0xffffffffULL)
                                             : (unsigned int)(acc[p][j] >> 32);
                float v = __uint_as_float(bits);
                int gc = cb + tn * 4 + j;
                if (bias) v += bias[gc];
                if (ACT == 1) v = fmaxf(v, 0.f);
                if (SPLIT) {
                    if (gc < L_DIM) C[(size_t)gr * L_DIM + gc] = v;
                    else            C2[(size_t)gr * L_DIM + gc - L_DIM] = v;
                } else {
                    C[(size_t)gr * Nc + gc] = v;
                }
            }
        }
    }
}

// pack [Wmu | Wlv] -> g_wmulv [256,128], biases -> g_bmulv
__global__ void k_pack(const float* __restrict__ Wmu, const float* __restrict__ Wlv,
                       const float* __restrict__ bmu, const float* __restrict__ blv) {
    int k = blockIdx.x;    // 256
    int j = threadIdx.x;   // 128
    g_wmulv[k * 128 + j] = (j < L_DIM) ? Wmu[k * L_DIM + j] : Wlv[k * L_DIM + j - L_DIM];
    if (k == 0) g_bmulv[j] = (j < L_DIM) ? bmu[j] : blv[j - L_DIM];
}

// fused: z = mu + eps*exp(0.5*lv); cap = sigmoid(z.Wcap + bcap). one warp per node.
__global__ void k_zcap(const float* __restrict__ mu, const float* __restrict__ lv,
                       const float* __restrict__ eps, const float* __restrict__ Wcap,
                       const float* __restrict__ bcap, float* __restrict__ cap, int n) {
    int gtid = blockIdx.x * blockDim.x + threadIdx.x;
    int node = gtid >> 5;
    int lane = gtid & 31;
    if (node >= n) return;
    size_t o0 = (size_t)node * L_DIM + lane;
    size_t o1 = o0 + 32;
    float z0 = fmaf(eps[o0], expf(0.5f * lv[o0]), mu[o0]);
    float z1 = fmaf(eps[o1], expf(0.5f * lv[o1]), mu[o1]);
    g_z[o0] = z0;
    g_z[o1] = z1;
    float a = z0 * Wcap[lane] + z1 * Wcap[lane + 32];
#pragma unroll
    for (int off = 16; off > 0; off >>= 1) a += __shfl_xor_sync(0xffffffffu, a, off);
    if (lane == 0) cap[node] = 1.f / (1.f + expf(-(a + bcap[0])));
}

// ---------------- launch ----------------
extern "C" void kernel_launch(void* const* d_in, const int* in_sizes, int n_in,
                              void* d_out, int out_size) {
    const int*   x    = (const int*)d_in[0];
    const int*   ei   = (const int*)d_in[1];
    const float* eps  = (const float*)d_in[2];
    const float* emb  = (const float*)d_in[3];
    const float* W1   = (const float*)d_in[4];
    const float* b1   = (const float*)d_in[5];
    const float* W2   = (const float*)d_in[6];
    const float* b2   = (const float*)d_in[7];
    const float* Wmu  = (const float*)d_in[8];
    const float* bmu  = (const float*)d_in[9];
    const float* Wlv  = (const float*)d_in[10];
    const float* blv  = (const float*)d_in[11];
    const float* W3   = (const float*)d_in[12];
    const float* b3   = (const float*)d_in[13];
    const float* W4   = (const float*)d_in[14];
    const float* b4   = (const float*)d_in[15];
    const float* Wcap = (const float*)d_in[16];
    const float* bcap = (const float*)d_in[17];

    const int N = in_sizes[0];
    const int E = in_sizes[1] / 2;

    float* out = (float*)d_out;
    float* out_recon = out;                                  // [N,128]
    float* out_cap   = out + (size_t)N * V_DIM;              // [N,1]
    float* out_mu    = out + (size_t)N * (V_DIM + 1);        // [N,64]
    float* out_lv    = out_mu + (size_t)N * L_DIM;           // [N,64]

    float* bufA;  cudaGetSymbolAddress((void**)&bufA, g_bufA);
    float* bufB;  cudaGetSymbolAddress((void**)&bufB, g_bufB);
    float* zbuf;  cudaGetSymbolAddress((void**)&zbuf, g_z);
    float* wmulv; cudaGetSymbolAddress((void**)&wmulv, g_wmulv);
    float* bmulv; cudaGetSymbolAddress((void**)&bmulv, g_bmulv);

    const int nb = (N + 1023) / 1024;

    // graph build
    k_zero_cnt<<<(N + 256) / 256, 256>>>(N);
    k_count<<<(E + 255) / 256, 256>>>(ei, E);
    k_dinv<<<(N + 255) / 256, 256>>>(N);
    k_scan1<<<nb, 1024>>>(N);
    k_scan2<<<1, SCAN_B>>>(N, nb);
    k_scan3<<<nb, 1024>>>(N);
    k_fill<<<(E + 255) / 256, 256>>>(ei, x, E);

    // layer 1: h1 = relu(agg(EW1[x]) + b1) with EW1 = emb@W1 (L1-resident table)
    k_ew1<<<V_DIM, H_DIM>>>(emb, W1);
    k_aggv<0><<<(N + 3) / 4, 256>>>(x, nullptr, b1, bufB, N);

    // layer 2: h2 = relu(agg(h1@W2) + b2)
    {
        dim3 grid((N + 127) / 128, H_DIM / 64);
        k_gemm<0, 0><<<grid, 256>>>(bufB, W2, nullptr, bufA, nullptr, N, H_DIM, H_DIM);
    }
    k_aggv<1><<<(N + 3) / 4, 256>>>(nullptr, bufA, b2, bufB, N);

    // heads: [mu | logvar] in one GEMM, split outputs
    k_pack<<<H_DIM, 2 * L_DIM>>>(Wmu, Wlv, bmu, blv);
    {
        dim3 grid((N + 127) / 128, (2 * L_DIM) / 64);
        k_gemm<0, 1><<<grid, 256>>>(bufB, wmulv, bmulv, out_mu, out_lv, N, H_DIM, 2 * L_DIM);
    }

    // z + capitalize head (fused)
    k_zcap<<<(N * 32 + 255) / 256, 256>>>(out_mu, out_lv, eps, Wcap, bcap, out_cap, N);

    // decoder: ZR = relu(z@W3+b3);  recon = ZR@W4+b4
    {
        dim3 grid((N + 127) / 128, H_DIM / 64);
        k_gemm<1, 0><<<grid, 256>>>(zbuf, W3, b3, bufA, nullptr, N, L_DIM, H_DIM);
    }
    {
        dim3 grid((N + 127) / 128, V_DIM / 64);
        k_gemm<0, 0><<<grid, 256>>>(bufA, W4, b4, out_recon, nullptr, N, H_DIM, V_DIM);
    }
}

// round 17
// speedup vs baseline: 1.0949x; 1.0949x over previous
#include <cuda_runtime.h>
#include <cuda_bf16.h>
#include <math.h>

// Problem constants (fixed by the dataset)
#define MAXN 50000
#define MAXE 800000
#define F_DIM 128
#define H_DIM 256
#define L_DIM 64
#define V_DIM 128
#define SCAN_B 64   // max scan blocks (ceil(50000/1024)=49)

// ---------------- scratch (allocation-free: __device__ globals) ----------------
__device__ int    g_cnt[MAXN + 1];
__device__ int    g_rowptr[MAXN + 1];
__device__ float  g_dinv[MAXN];
__device__ int    g_bsum[SCAN_B];
__device__ int    g_boff[SCAN_B];
__device__ float2 g_e1[MAXE];   // (x[src] as float-bits, dinv[src])  — layer-1 edges
__device__ float2 g_e2[MAXE];   // (src as float-bits,   dinv[src])  — layer-2 edges
__device__ float  g_ew1[V_DIM * H_DIM];           // emb @ W1  [128,256]
__device__ float  g_wmulv[H_DIM * (2 * L_DIM)];   // [Wmu | Wlv]  [256,128]
__device__ float  g_bmulv[2 * L_DIM];
__device__ float  g_bufA[(size_t)MAXN * H_DIM];   // XW2 / ZR
__device__ float  g_bufB[(size_t)MAXN * H_DIM];   // h1 / h2
__device__ float  g_z[(size_t)MAXN * L_DIM];

// ---------------- f32x2 packed-FMA helpers ----------------
#define FFMA2(acc, a, b) \
    asm("fma.rn.f32x2 %0, %1, %2, %0;" : "+l"(acc) : "l"(a), "l"(b))

__device__ __forceinline__ unsigned long long splat_f32x2(float v) {
    unsigned long long r;
    unsigned int u = __float_as_uint(v);
    asm("mov.b64 %0, {%1, %2};" : "=l"(r) : "r"(u), "r"(u));
    return r;
}

// ---------------- graph build ----------------
__global__ void k_zero_cnt(int n) {
    int i = blockIdx.x * blockDim.x + threadIdx.x;
    if (i <= n) g_cnt[i] = 0;
}

__global__ void k_count(const int* __restrict__ ei, int E) {
    int e = blockIdx.x * blockDim.x + threadIdx.x;
    if (e < E) atomicAdd(&g_cnt[ei[E + e]], 1);  // dst row
}

__global__ void k_dinv(int n) {
    int i = blockIdx.x * blockDim.x + threadIdx.x;
    if (i < n) g_dinv[i] = rsqrtf((float)(g_cnt[i] + 1));  // +1 self-loop
}

__global__ void k_scan1(int n) {
    __shared__ int sh[1024];
    int t = threadIdx.x;
    int i = blockIdx.x * 1024 + t;
    int v = (i < n) ? g_cnt[i] : 0;
    sh[t] = v;
    __syncthreads();
    for (int off = 1; off < 1024; off <<= 1) {
        int add = (t >= off) ? sh[t - off] : 0;
        __syncthreads();
        sh[t] += add;
        __syncthreads();
    }
    if (i < n) { g_rowptr[i] = sh[t] - v; g_cnt[i] = 0; }
    if (t == 1023) g_bsum[blockIdx.x] = sh[1023];
}

__global__ void k_scan2(int n, int nb) {
    __shared__ int sh[SCAN_B];
    int t = threadIdx.x;  // 64 threads
    int v = (t < nb) ? g_bsum[t] : 0;
    sh[t] = v;
    __syncthreads();
    for (int off = 1; off < SCAN_B; off <<= 1) {
        int add = (t >= off) ? sh[t - off] : 0;
        __syncthreads();
        sh[t] += add;
        __syncthreads();
    }
    if (t < nb) g_boff[t] = sh[t] - v;        // exclusive (race-free)
    if (t == SCAN_B - 1) g_rowptr[n] = sh[SCAN_B - 1];
}

__global__ void k_scan3(int n) {
    int i = blockIdx.x * 1024 + threadIdx.x;
    if (i < n) g_rowptr[i] += g_boff[blockIdx.x];
}

__global__ void k_fill(const int* __restrict__ ei, const int* __restrict__ x, int E) {
    int e = blockIdx.x * blockDim.x + threadIdx.x;
    if (e < E) {
        int s = ei[e];
        int d = ei[E + e];
        int pos = g_rowptr[d] + atomicAdd(&g_cnt[d], 1);
        float w = g_dinv[s];
        g_e2[pos] = make_float2(__int_as_float(s), w);
        g_e1[pos] = make_float2(__int_as_float(x[s]), w);
    }
}

// ---------------- layer 1 ----------------
// EW1[v,h] = sum_k emb[v,k] * W1[k,h]   (128x128 @ 128x256)
__global__ void k_ew1(const float* __restrict__ emb, const float* __restrict__ W1) {
    int v = blockIdx.x;     // 128
    int h = threadIdx.x;    // 256
    float acc = 0.f;
#pragma unroll 8
    for (int k = 0; k < F_DIM; k++) acc += emb[v * F_DIM + k] * W1[k * H_DIM + h];
    g_ew1[v * H_DIM + h] = acc;
}

// ---------------- vectorized aggregation: 4 nodes/block, 64 threads/node, float4 ----------------
template <int MODE>
__global__ void __launch_bounds__(256)
k_aggv(const int* __restrict__ x, const float* __restrict__ in,
       const float* __restrict__ bias, float* __restrict__ out, int n) {
    int node = blockIdx.x * 4 + (threadIdx.x >> 6);
    int f4 = threadIdx.x & 63;   // float4 lane: covers 256 floats
    if (node >= n) return;
    float di = g_dinv[node];
    const float4* tab = (MODE == 0) ? (const float4*)g_ew1 : (const float4*)in;

    int self = (MODE == 0) ? x[node] : node;
    float4 a = tab[(size_t)self * 64 + f4];
    float4 acc;
    acc.x = a.x * di; acc.y = a.y * di; acc.z = a.z * di; acc.w = a.w * di;

    int beg = g_rowptr[node], end = g_rowptr[node + 1];
    const float2* el = (MODE == 0) ? g_e1 : g_e2;
    for (int e = beg; e < end; e++) {
        float2 p = el[e];
        int s = __float_as_int(p.x);
        float w = p.y;
        float4 r = tab[(size_t)s * 64 + f4];
        acc.x = fmaf(r.x, w, acc.x);
        acc.y = fmaf(r.y, w, acc.y);
        acc.z = fmaf(r.z, w, acc.z);
        acc.w = fmaf(r.w, w, acc.w);
    }
    float4 b4 = ((const float4*)bias)[f4];
    float4 o;
    o.x = fmaxf(fmaf(di, acc.x, b4.x), 0.f);
    o.y = fmaxf(fmaf(di, acc.y, b4.y), 0.f);
    o.z = fmaxf(fmaf(di, acc.z, b4.z), 0.f);
    o.w = fmaxf(fmaf(di, acc.w, b4.w), 0.f);
    ((float4*)out)[(size_t)node * 64 + f4] = o;
}

// ---------------- 8x8-tile packed-f32x2 SGEMM ----------------
// C[M,Nc] = A[M,K] @ B[K,Nc] (+bias)(+relu). BM=128 BN=128 BK=16, 256 threads.
// Per-thread 8x8 tile: rows {tm*4+0..3, 64+tm*4+0..3}, cols {tn*4+0..3, 64+tn*4+0..3}.
// 4 row-pairs x 8 cols of f32x2 accumulators; each f32x2 lane is an exact fp32 FMA.
// K%16==0, Nc%128==0. SPLIT: cols [0,64)->C (mu), [64,128)->C2 (lv), row-stride 64.
template <int ACT, int SPLIT>
__global__ void __launch_bounds__(256, 2)
k_gemm(const float* __restrict__ A, const float* __restrict__ B,
       const float* __restrict__ bias, float* __restrict__ C, float* __restrict__ C2,
       int M, int K, int Nc) {
    const int BM = 128, BN = 128, BK = 16;
    __shared__ __align__(16) float As[BK][BM];      // transposed: As[k][m]
    __shared__ __align__(16) float Bs[BK][BN + 4];  // row stride 132 floats (528B, 16B-aligned)
    int t = threadIdx.x;
    int rb = blockIdx.x * BM;
    int cb = blockIdx.y * BN;

    unsigned long long acc[4][8];
#pragma unroll
    for (int p = 0; p < 4; p++)
#pragma unroll
        for (int j = 0; j < 8; j++) acc[p][j] = 0ULL;

    int arow = t >> 2;          // 0..63  (A rows arow, arow+64)
    int acol = (t & 3) * 4;     // 0,4,8,12
    int brow = t >> 5;          // 0..7   (B rows brow, brow+8)
    int bcol = (t & 31) * 4;    // 0..124
    int tm = t >> 4;            // 0..15  (row group)
    int tn = t & 15;            // 0..15  (col group)

    for (int kb = 0; kb < K; kb += BK) {
#pragma unroll
        for (int rr = 0; rr < 2; rr++) {
            int r = arow + rr * 64;
            int gr = rb + r;
            float4 v = make_float4(0.f, 0.f, 0.f, 0.f);
            if (gr < M) v = *(const float4*)&A[(size_t)gr * K + kb + acol];
            As[acol + 0][r] = v.x;
            As[acol + 1][r] = v.y;
            As[acol + 2][r] = v.z;
            As[acol + 3][r] = v.w;
        }
#pragma unroll
        for (int rr = 0; rr < 2; rr++) {
            int r = brow + rr * 8;
            *(float4*)&Bs[r][bcol] = *(const float4*)&B[(size_t)(kb + r) * Nc + cb + bcol];
        }
        __syncthreads();

#pragma unroll
        for (int k = 0; k < BK; k++) {
            ulonglong2 a01 = *(const ulonglong2*)&As[k][tm * 4];       // row pairs (0,1),(2,3)
            ulonglong2 a23 = *(const ulonglong2*)&As[k][64 + tm * 4];  // row pairs (64+0,1),(64+2,3)
            float4 b0 = *(const float4*)&Bs[k][tn * 4];
            float4 b1 = *(const float4*)&Bs[k][64 + tn * 4];
            unsigned long long bp0 = splat_f32x2(b0.x);
            unsigned long long bp1 = splat_f32x2(b0.y);
            unsigned long long bp2 = splat_f32x2(b0.z);
            unsigned long long bp3 = splat_f32x2(b0.w);
            unsigned long long bp4 = splat_f32x2(b1.x);
            unsigned long long bp5 = splat_f32x2(b1.y);
            unsigned long long bp6 = splat_f32x2(b1.z);
            unsigned long long bp7 = splat_f32x2(b1.w);
            FFMA2(acc[0][0], a01.x, bp0); FFMA2(acc[0][1], a01.x, bp1);
            FFMA2(acc[0][2], a01.x, bp2); FFMA2(acc[0][3], a01.x, bp3);
            FFMA2(acc[0][4], a01.x, bp4); FFMA2(acc[0][5], a01.x, bp5);
            FFMA2(acc[0][6], a01.x, bp6); FFMA2(acc[0][7], a01.x, bp7);
            FFMA2(acc[1][0], a01.y, bp0); FFMA2(acc[1][1], a01.y, bp1);
            FFMA2(acc[1][2], a01.y, bp2); FFMA2(acc[1][3], a01.y, bp3);
            FFMA2(acc[1][4], a01.y, bp4); FFMA2(acc[1][5], a01.y, bp5);
            FFMA2(acc[1][6], a01.y, bp6); FFMA2(acc[1][7], a01.y, bp7);
            FFMA2(acc[2][0], a23.x, bp0); FFMA2(acc[2][1], a23.x, bp1);
            FFMA2(acc[2][2], a23.x, bp2); FFMA2(acc[2][3], a23.x, bp3);
            FFMA2(acc[2][4], a23.x, bp4); FFMA2(acc[2][5], a23.x, bp5);
            FFMA2(acc[2][6], a23.x, bp6); FFMA2(acc[2][7], a23.x, bp7);
            FFMA2(acc[3][0], a23.y, bp0); FFMA2(acc[3][1], a23.y, bp1);
            FFMA2(acc[3][2], a23.y, bp2); FFMA2(acc[3][3], a23.y, bp3);
            FFMA2(acc[3][4], a23.y, bp4); FFMA2(acc[3][5], a23.y, bp5);
            FFMA2(acc[3][6], a23.y, bp6); FFMA2(acc[3][7], a23.y, bp7);
        }
        __syncthreads();
    }

#pragma unroll
    for (int p = 0; p < 4; p++) {
        int baseRow = (p < 2) ? (tm * 4 + 2 * p) : (64 + tm * 4 + 2 * (p - 2));
#pragma unroll
        for (int h = 0; h < 2; h++) {
            int gr = rb + baseRow + h;
            if (gr >= M) continue;
#pragma unroll
            for (int j = 0; j < 8; j++) {
                unsigned int bits = (h == 0) ? (unsigned int)(acc[p][j] & 0xffffffffULL)
                                             : (unsigned int)(acc[p][j] >> 32);
                float v = __uint_as_float(bits);
                int gc = cb + ((j < 4) ? (tn * 4 + j) : (64 + tn * 4 + (j - 4)));
                if (bias) v += bias[gc];
                if (ACT == 1) v = fmaxf(v, 0.f);
                if (SPLIT) {
                    if (gc < L_DIM) C[(size_t)gr * L_DIM + gc] = v;
                    else            C2[(size_t)gr * L_DIM + gc - L_DIM] = v;
                } else {
                    C[(size_t)gr * Nc + gc] = v;
                }
            }
        }
    }
}

// pack [Wmu | Wlv] -> g_wmulv [256,128], biases -> g_bmulv
__global__ void k_pack(const float* __restrict__ Wmu, const float* __restrict__ Wlv,
                       const float* __restrict__ bmu, const float* __restrict__ blv) {
    int k = blockIdx.x;    // 256
    int j = threadIdx.x;   // 128
    g_wmulv[k * 128 + j] = (j < L_DIM) ? Wmu[k * L_DIM + j] : Wlv[k * L_DIM + j - L_DIM];
    if (k == 0) g_bmulv[j] = (j < L_DIM) ? bmu[j] : blv[j - L_DIM];
}

// fused: z = mu + eps*exp(0.5*logvar); cap = sigmoid(z.Wcap + bcap). one warp per node.
__global__ void k_zcap(const float* __restrict__ mu, const float* __restrict__ lv,
                       const float* __restrict__ eps, const float* __restrict__ Wcap,
                       const float* __restrict__ bcap, float* __restrict__ cap, int n) {
    int gtid = blockIdx.x * blockDim.x + threadIdx.x;
    int node = gtid >> 5;
    int lane = gtid & 31;
    if (node >= n) return;
    size_t o0 = (size_t)node * L_DIM + lane;
    size_t o1 = o0 + 32;
    float z0 = fmaf(eps[o0], expf(0.5f * lv[o0]), mu[o0]);
    float z1 = fmaf(eps[o1], expf(0.5f * lv[o1]), mu[o1]);
    g_z[o0] = z0;
    g_z[o1] = z1;
    float a = z0 * Wcap[lane] + z1 * Wcap[lane + 32];
#pragma unroll
    for (int off = 16; off > 0; off >>= 1) a += __shfl_xor_sync(0xffffffffu, a, off);
    if (lane == 0) cap[node] = 1.f / (1.f + expf(-(a + bcap[0])));
}

// ---------------- launch ----------------
extern "C" void kernel_launch(void* const* d_in, const int* in_sizes, int n_in,
                              void* d_out, int out_size) {
    const int*   x    = (const int*)d_in[0];
    const int*   ei   = (const int*)d_in[1];
    const float* eps  = (const float*)d_in[2];
    const float* emb  = (const float*)d_in[3];
    const float* W1   = (const float*)d_in[4];
    const float* b1   = (const float*)d_in[5];
    const float* W2   = (const float*)d_in[6];
    const float* b2   = (const float*)d_in[7];
    const float* Wmu  = (const float*)d_in[8];
    const float* bmu  = (const float*)d_in[9];
    const float* Wlv  = (const float*)d_in[10];
    const float* blv  = (const float*)d_in[11];
    const float* W3   = (const float*)d_in[12];
    const float* b3   = (const float*)d_in[13];
    const float* W4   = (const float*)d_in[14];
    const float* b4   = (const float*)d_in[15];
    const float* Wcap = (const float*)d_in[16];
    const float* bcap = (const float*)d_in[17];

    const int N = in_sizes[0];
    const int E = in_sizes[1] / 2;

    float* out = (float*)d_out;
    float* out_recon = out;                                  // [N,128]
    float* out_cap   = out + (size_t)N * V_DIM;              // [N,1]
    float* out_mu    = out + (size_t)N * (V_DIM + 1);        // [N,64]
    float* out_lv    = out_mu + (size_t)N * L_DIM;           // [N,64]

    float* bufA;  cudaGetSymbolAddress((void**)&bufA, g_bufA);
    float* bufB;  cudaGetSymbolAddress((void**)&bufB, g_bufB);
    float* zbuf;  cudaGetSymbolAddress((void**)&zbuf, g_z);
    float* wmulv; cudaGetSymbolAddress((void**)&wmulv, g_wmulv);
    float* bmulv; cudaGetSymbolAddress((void**)&bmulv, g_bmulv);

    const int nb = (N + 1023) / 1024;

    // graph build
    k_zero_cnt<<<(N + 256) / 256, 256>>>(N);
    k_count<<<(E + 255) / 256, 256>>>(ei, E);
    k_dinv<<<(N + 255) / 256, 256>>>(N);
    k_scan1<<<nb, 1024>>>(N);
    k_scan2<<<1, SCAN_B>>>(N, nb);
    k_scan3<<<nb, 1024>>>(N);
    k_fill<<<(E + 255) / 256, 256>>>(ei, x, E);

    // layer 1: h1 = relu(agg(EW1[x]) + b1) with EW1 = emb@W1 (L1-resident table)
    k_ew1<<<V_DIM, H_DIM>>>(emb, W1);
    k_aggv<0><<<(N + 3) / 4, 256>>>(x, nullptr, b1, bufB, N);

    // layer 2: h2 = relu(agg(h1@W2) + b2)
    {
        dim3 grid((N + 127) / 128, H_DIM / 128);
        k_gemm<0, 0><<<grid, 256>>>(bufB, W2, nullptr, bufA, nullptr, N, H_DIM, H_DIM);
    }
    k_aggv<1><<<(N + 3) / 4, 256>>>(nullptr, bufA, b2, bufB, N);

    // heads: [mu | logvar] in one GEMM, split outputs
    k_pack<<<H_DIM, 2 * L_DIM>>>(Wmu, Wlv, bmu, blv);
    {
        dim3 grid((N + 127) / 128, (2 * L_DIM) / 128);
        k_gemm<0, 1><<<grid, 256>>>(bufB, wmulv, bmulv, out_mu, out_lv, N, H_DIM, 2 * L_DIM);
    }

    // z + capitalize head (fused)
    k_zcap<<<(N * 32 + 255) / 256, 256>>>(out_mu, out_lv, eps, Wcap, bcap, out_cap, N);

    // decoder: ZR = relu(z@W3+b3);  recon = ZR@W4+b4
    {
        dim3 grid((N + 127) / 128, H_DIM / 128);
        k_gemm<1, 0><<<grid, 256>>>(zbuf, W3, b3, bufA, nullptr, N, L_DIM, H_DIM);
    }
    {
        dim3 grid((N + 127) / 128, V_DIM / 128);
        k_gemm<0, 0><<<grid, 256>>>(bufA, W4, b4, out_recon, nullptr, N, H_DIM, V_DIM);
    }
}